// round 2
// baseline (speedup 1.0000x reference)
#include <cuda_runtime.h>
#include <math.h>
#include <stdint.h>

// ---------------------------------------------------------------------------
// TrajectoryGAT: 2x GATConv (heads=1) + mean pool + linear + log_softmax
//   N=100000 nodes, E=1600000 edges per layer, HID=128, G=256 graphs, OUT=2
//
// Design: dst-CSR built per call (hist -> scan -> scatter), then warp-per-dst
// aggregation with online softmax (no float atomics in the hot path).
// kernel_launch contains ONLY kernel launches (graph-capture safe); all
// scratch lives in __device__ globals referenced directly by the kernels.
// ---------------------------------------------------------------------------

#define N_NODES 100000
#define N_EDGES 1600000
#define HID 128
#define SCAN_B 1024

// ---- device scratch (static allocation: allowed) ----
__device__ float g_h[(size_t)N_NODES * HID];     // node features after W
__device__ float g_acc[(size_t)N_NODES * HID];   // aggregation output
__device__ float g_as[N_NODES];                  // a_src dot per node
__device__ float g_ad[N_NODES];                  // a_dst dot per node
__device__ int   g_cnt[N_NODES];
__device__ int   g_row[N_NODES + 1];
__device__ int   g_cur[N_NODES];
__device__ int   g_csrc[N_EDGES];                // src ids grouped by dst
__device__ int   g_bsum[1024];

// ---------------------------------------------------------------------------
__global__ void zero_cnt_kernel(int n) {
    for (int i = blockIdx.x * blockDim.x + threadIdx.x; i < n; i += gridDim.x * blockDim.x)
        g_cnt[i] = 0;
}

__global__ void hist_kernel(const int* __restrict__ dst, int E) {
    for (int i = blockIdx.x * blockDim.x + threadIdx.x; i < E; i += gridDim.x * blockDim.x)
        atomicAdd(&g_cnt[dst[i]], 1);
}

// block-level inclusive scan -> exclusive row, per-block totals
__global__ void scan1_kernel(int n) {
    __shared__ int sh[SCAN_B];
    int i = blockIdx.x * SCAN_B + threadIdx.x;
    int v = (i < n) ? g_cnt[i] : 0;
    sh[threadIdx.x] = v;
    __syncthreads();
    for (int off = 1; off < SCAN_B; off <<= 1) {
        int t = (threadIdx.x >= off) ? sh[threadIdx.x - off] : 0;
        __syncthreads();
        sh[threadIdx.x] += t;
        __syncthreads();
    }
    if (i < n) g_row[i] = sh[threadIdx.x] - v;          // exclusive
    if (threadIdx.x == SCAN_B - 1) g_bsum[blockIdx.x] = sh[SCAN_B - 1];
}

// single-block scan of block sums (nb <= 128), writes grand total to row[n]
__global__ void scan2_kernel(int nb, int n) {
    __shared__ int sh[128];
    int t = threadIdx.x;
    int v = (t < nb) ? g_bsum[t] : 0;
    sh[t] = v;
    __syncthreads();
    for (int off = 1; off < 128; off <<= 1) {
        int u = (t >= off) ? sh[t - off] : 0;
        __syncthreads();
        sh[t] += u;
        __syncthreads();
    }
    if (t < nb) g_bsum[t] = sh[t] - v;                  // exclusive
    if (t == 127) g_row[n] = sh[127];                   // row[N] = E
}

__global__ void scan3_kernel(int n) {
    for (int i = blockIdx.x * blockDim.x + threadIdx.x; i < n; i += gridDim.x * blockDim.x) {
        int r = g_row[i] + g_bsum[i >> 10];
        g_row[i] = r;
        g_cur[i] = r;
    }
}

__global__ void scatter_kernel(const int* __restrict__ src, const int* __restrict__ dst, int E) {
    for (int i = blockIdx.x * blockDim.x + threadIdx.x; i < E; i += gridDim.x * blockDim.x) {
        int p = atomicAdd(&g_cur[dst[i]], 1);
        g_csrc[p] = src[i];
    }
}

// ---------------------------------------------------------------------------
// Layer-1 transform: h = x @ W1  (IN=9), plus attention dots. One warp/node.
__global__ void transform1_kernel(const float* __restrict__ x, const float* __restrict__ W,
                                  const float* __restrict__ atts, const float* __restrict__ attd,
                                  int n) {
    int node = (blockIdx.x * blockDim.x + threadIdx.x) >> 5;
    int lane = threadIdx.x & 31;
    if (node >= n) return;
    float xv = (lane < 9) ? x[(size_t)node * 9 + lane] : 0.f;
    float4 acc = make_float4(0.f, 0.f, 0.f, 0.f);
#pragma unroll
    for (int k = 0; k < 9; k++) {
        float xk = __shfl_sync(0xffffffffu, xv, k);
        float4 w = *(const float4*)(W + k * HID + lane * 4);
        acc.x = fmaf(xk, w.x, acc.x);
        acc.y = fmaf(xk, w.y, acc.y);
        acc.z = fmaf(xk, w.z, acc.z);
        acc.w = fmaf(xk, w.w, acc.w);
    }
    *(float4*)(g_h + (size_t)node * HID + lane * 4) = acc;
    float4 s4 = *(const float4*)(atts + lane * 4);
    float4 d4 = *(const float4*)(attd + lane * 4);
    float ps = acc.x * s4.x + acc.y * s4.y + acc.z * s4.z + acc.w * s4.w;
    float pd = acc.x * d4.x + acc.y * d4.y + acc.z * d4.z + acc.w * d4.w;
#pragma unroll
    for (int off = 16; off >= 1; off >>= 1) {
        ps += __shfl_xor_sync(0xffffffffu, ps, off);
        pd += __shfl_xor_sync(0xffffffffu, pd, off);
    }
    if (lane == 0) { g_as[node] = ps; g_ad[node] = pd; }
}

// attention dots for layer 2 (g_h already holds h2 = acc @ W2). One warp/node.
__global__ void att_kernel(const float* __restrict__ atts, const float* __restrict__ attd, int n) {
    int node = (blockIdx.x * blockDim.x + threadIdx.x) >> 5;
    int lane = threadIdx.x & 31;
    if (node >= n) return;
    float4 hv = *(const float4*)(g_h + (size_t)node * HID + lane * 4);
    float4 s4 = *(const float4*)(atts + lane * 4);
    float4 d4 = *(const float4*)(attd + lane * 4);
    float ps = hv.x * s4.x + hv.y * s4.y + hv.z * s4.z + hv.w * s4.w;
    float pd = hv.x * d4.x + hv.y * d4.y + hv.z * d4.z + hv.w * d4.w;
#pragma unroll
    for (int off = 16; off >= 1; off >>= 1) {
        ps += __shfl_xor_sync(0xffffffffu, ps, off);
        pd += __shfl_xor_sync(0xffffffffu, pd, off);
    }
    if (lane == 0) { g_as[node] = ps; g_ad[node] = pd; }
}

// ---------------------------------------------------------------------------
// Dst-centric aggregation with online softmax. One warp per dst node.
// out[dst] = (sum_e exp(alpha_e - m) * h[src_e]) / (sum_e exp(alpha_e - m) + 1e-16) + bias
template <bool RELU>
__global__ void aggregate_kernel(const float* __restrict__ bias, int n) {
    int node = (blockIdx.x * blockDim.x + threadIdx.x) >> 5;
    int lane = threadIdx.x & 31;
    if (node >= n) return;
    int start = g_row[node], end = g_row[node + 1];
    float ad = g_ad[node];
    float m = -INFINITY, s = 0.f;
    float4 acc = make_float4(0.f, 0.f, 0.f, 0.f);
    for (int base = start; base < end; base += 32) {
        int nloc = min(32, end - base);
        int srcl = 0;
        float al = 0.f;
        if (lane < nloc) {
            srcl = g_csrc[base + lane];
            float a = g_as[srcl] + ad;
            al = (a >= 0.f) ? a : 0.2f * a;   // leaky_relu(., 0.2)
        }
        for (int t = 0; t < nloc; ++t) {
            int sidx = __shfl_sync(0xffffffffu, srcl, t);
            float alpha = __shfl_sync(0xffffffffu, al, t);
            float4 hv = *(const float4*)(g_h + (size_t)sidx * HID + lane * 4);
            if (alpha <= m) {
                float w = __expf(alpha - m);
                s += w;
                acc.x = fmaf(w, hv.x, acc.x);
                acc.y = fmaf(w, hv.y, acc.y);
                acc.z = fmaf(w, hv.z, acc.z);
                acc.w = fmaf(w, hv.w, acc.w);
            } else {
                float sc = __expf(m - alpha);   // 0 on first edge (m = -inf)
                s = fmaf(s, sc, 1.f);
                acc.x = fmaf(acc.x, sc, hv.x);
                acc.y = fmaf(acc.y, sc, hv.y);
                acc.z = fmaf(acc.z, sc, hv.z);
                acc.w = fmaf(acc.w, sc, hv.w);
                m = alpha;
            }
        }
    }
    float inv = 1.f / (s + 1e-16f);
    float4 b = *(const float4*)(bias + lane * 4);
    float4 o;
    o.x = fmaf(acc.x, inv, b.x);
    o.y = fmaf(acc.y, inv, b.y);
    o.z = fmaf(acc.z, inv, b.z);
    o.w = fmaf(acc.w, inv, b.w);
    if (RELU) {
        o.x = fmaxf(o.x, 0.f); o.y = fmaxf(o.y, 0.f);
        o.z = fmaxf(o.z, 0.f); o.w = fmaxf(o.w, 0.f);
    }
    *(float4*)(g_acc + (size_t)node * HID + lane * 4) = o;
}

// ---------------------------------------------------------------------------
// g_h[M,128] = g_acc[M,128] @ B[128,128], fp32 tiled. BM=64, BN=128, BK=16.
__global__ __launch_bounds__(256) void gemm128_kernel(const float* __restrict__ B, int M) {
    __shared__ float As[16][64];
    __shared__ float Bs[16][128];
    int tid = threadIdx.x;
    int tx = tid & 31;   // N groups of 4
    int ty = tid >> 5;   // M groups of 8
    int base = blockIdx.x * 64;
    float acc[8][4];
#pragma unroll
    for (int i = 0; i < 8; i++)
#pragma unroll
        for (int j = 0; j < 4; j++) acc[i][j] = 0.f;

    int am = tid >> 2;
    int ak = (tid & 3) * 4;
    for (int k0 = 0; k0 < 128; k0 += 16) {
        float4 av = make_float4(0.f, 0.f, 0.f, 0.f);
        if (base + am < M)
            av = *(const float4*)(g_acc + (size_t)(base + am) * 128 + k0 + ak);
        As[ak + 0][am] = av.x;
        As[ak + 1][am] = av.y;
        As[ak + 2][am] = av.z;
        As[ak + 3][am] = av.w;
#pragma unroll
        for (int r = 0; r < 2; r++) {
            int f = tid + r * 256;
            int bk = f >> 5, bn = (f & 31) * 4;
            *(float4*)&Bs[bk][bn] = *(const float4*)(B + (size_t)(k0 + bk) * 128 + bn);
        }
        __syncthreads();
#pragma unroll
        for (int k = 0; k < 16; k++) {
            float4 aa = *(const float4*)&As[k][ty * 8];
            float4 ab = *(const float4*)&As[k][ty * 8 + 4];
            float4 bv = *(const float4*)&Bs[k][tx * 4];
            float a[8] = {aa.x, aa.y, aa.z, aa.w, ab.x, ab.y, ab.z, ab.w};
            float b[4] = {bv.x, bv.y, bv.z, bv.w};
#pragma unroll
            for (int i = 0; i < 8; i++)
#pragma unroll
                for (int j = 0; j < 4; j++) acc[i][j] = fmaf(a[i], b[j], acc[i][j]);
        }
        __syncthreads();
    }
#pragma unroll
    for (int i = 0; i < 8; i++) {
        int mrow = base + ty * 8 + i;
        if (mrow < M) {
            float4 o = make_float4(acc[i][0], acc[i][1], acc[i][2], acc[i][3]);
            *(float4*)(g_h + (size_t)mrow * 128 + tx * 4) = o;
        }
    }
}

// ---------------------------------------------------------------------------
// Mean pool by (sorted) batch id + classifier + log_softmax. One block/graph.
__global__ __launch_bounds__(512) void pool_kernel(const int* __restrict__ batch,
                                                   const float* __restrict__ Wc,
                                                   const float* __restrict__ bc,
                                                   float* __restrict__ out, int N) {
    int g = blockIdx.x;
    int t = threadIdx.x;
    int c = t & 127;
    int part = t >> 7;
    // boundaries via lower_bound (batch is sorted)
    int lo = 0, hi = N;
    while (lo < hi) { int mid = (lo + hi) >> 1; if (batch[mid] < g) lo = mid + 1; else hi = mid; }
    int start = lo;
    hi = N;
    while (lo < hi) { int mid = (lo + hi) >> 1; if (batch[mid] < g + 1) lo = mid + 1; else hi = mid; }
    int end = lo;

    float sum = 0.f;
    for (int nd = start + part; nd < end; nd += 4) sum += g_acc[(size_t)nd * HID + c];
    __shared__ float sh[512];
    sh[t] = sum;
    __syncthreads();
    if (t < 128) {
        float s = sh[t] + sh[t + 128] + sh[t + 256] + sh[t + 384];
        float cnt = (float)(end - start);
        if (cnt < 1.f) cnt = 1.f;
        float p = s / cnt;
        sh[t] = p * Wc[c * 2 + 0];
        sh[t + 128] = p * Wc[c * 2 + 1];
    }
    __syncthreads();
    for (int off = 64; off >= 1; off >>= 1) {
        if (t < off) { sh[t] += sh[t + off]; sh[128 + t] += sh[128 + t + off]; }
        __syncthreads();
    }
    if (t == 0) {
        float l0 = sh[0] + bc[0];
        float l1 = sh[128] + bc[1];
        float mx = fmaxf(l0, l1);
        float lse = mx + logf(expf(l0 - mx) + expf(l1 - mx));
        out[g * 2 + 0] = l0 - lse;
        out[g * 2 + 1] = l1 - lse;
    }
}

// ---------------------------------------------------------------------------
static void build_csr(const int* ei, int E, int N) {
    const int* src = ei;
    const int* dst = ei + E;
    int nb_scan = (N + SCAN_B - 1) / SCAN_B;
    zero_cnt_kernel<<<(N + 255) / 256, 256>>>(N);
    hist_kernel<<<(E + 255) / 256, 256>>>(dst, E);
    scan1_kernel<<<nb_scan, SCAN_B>>>(N);
    scan2_kernel<<<1, 128>>>(nb_scan, N);
    scan3_kernel<<<(N + 255) / 256, 256>>>(N);
    scatter_kernel<<<(E + 255) / 256, 256>>>(src, dst, E);
}

extern "C" void kernel_launch(void* const* d_in, const int* in_sizes, int n_in,
                              void* d_out, int out_size) {
    const float* x      = (const float*)d_in[0];
    const int*   ei_s   = (const int*)d_in[1];
    const int*   ei_t   = (const int*)d_in[3];
    const int*   batch  = (const int*)d_in[5];
    const float* W1     = (const float*)d_in[6];
    const float* atts1  = (const float*)d_in[7];
    const float* attd1  = (const float*)d_in[8];
    const float* b1     = (const float*)d_in[9];
    const float* W2     = (const float*)d_in[10];
    const float* atts2  = (const float*)d_in[11];
    const float* attd2  = (const float*)d_in[12];
    const float* b2     = (const float*)d_in[13];
    const float* Wc     = (const float*)d_in[14];
    const float* bc     = (const float*)d_in[15];
    float* out = (float*)d_out;

    const int N = in_sizes[0] / 9;
    const int E = in_sizes[1] / 2;
    const int G = out_size / 2;

    int warp_blocks = (N * 32 + 255) / 256;

    // ---- layer 1 (spatial) ----
    transform1_kernel<<<warp_blocks, 256>>>(x, W1, atts1, attd1, N);
    build_csr(ei_s, E, N);
    aggregate_kernel<true><<<warp_blocks, 256>>>(b1, N);

    // ---- layer 2 (temporal) ----
    gemm128_kernel<<<(N + 63) / 64, 256>>>(W2, N);
    att_kernel<<<warp_blocks, 256>>>(atts2, attd2, N);
    build_csr(ei_t, E, N);
    aggregate_kernel<false><<<warp_blocks, 256>>>(b2, N);

    // ---- pool + classify + log_softmax ----
    pool_kernel<<<G, 512>>>(batch, Wc, bc, out, N);
}

// round 3
// speedup vs baseline: 1.0009x; 1.0009x over previous
#include <cuda_runtime.h>
#include <cuda_bf16.h>
#include <math.h>
#include <stdint.h>

// ---------------------------------------------------------------------------
// TrajectoryGAT: 2x GATConv (heads=1) + mean pool + linear + log_softmax
//   N=100000, E=1600000/layer, HID=128, G=256, OUT=2
//
// R2 changes vs R1:
//   - gathered feature array stored as packed bf16 (halves L2 gather traffic)
//   - attention dots fused into GEMM epilogue (att_kernel removed)
//   - aggregate inner loop unrolled x4 for memory-level parallelism
// ---------------------------------------------------------------------------

#define N_NODES 100000
#define N_EDGES 1600000
#define HID 128
#define SCAN_B 1024

// ---- device scratch ----
__device__ uint2 g_hb[(size_t)N_NODES * 32];     // h in bf16: 128ch = 32 x uint2(4xbf16)
__device__ float g_acc[(size_t)N_NODES * HID];   // aggregation output (fp32)
__device__ float g_as[N_NODES];
__device__ float g_ad[N_NODES];
__device__ int   g_cnt[N_NODES];
__device__ int   g_row[N_NODES + 1];
__device__ int   g_cur[N_NODES];
__device__ int   g_csrc[N_EDGES];
__device__ int   g_bsum[1024];

__device__ __forceinline__ uint2 pack4bf(float a, float b, float c, float d) {
    uint2 r;
    __nv_bfloat162 p0 = __float22bfloat162_rn(make_float2(a, b));
    __nv_bfloat162 p1 = __float22bfloat162_rn(make_float2(c, d));
    r.x = *(unsigned*)&p0;
    r.y = *(unsigned*)&p1;
    return r;
}

__device__ __forceinline__ float4 unpack4bf(uint2 v) {
    float2 f0 = __bfloat1622float2(*(__nv_bfloat162*)&v.x);
    float2 f1 = __bfloat1622float2(*(__nv_bfloat162*)&v.y);
    return make_float4(f0.x, f0.y, f1.x, f1.y);
}

// ---------------------------------------------------------------------------
__global__ void zero_cnt_kernel(int n) {
    for (int i = blockIdx.x * blockDim.x + threadIdx.x; i < n; i += gridDim.x * blockDim.x)
        g_cnt[i] = 0;
}

__global__ void hist_kernel(const int* __restrict__ dst, int E) {
    for (int i = blockIdx.x * blockDim.x + threadIdx.x; i < E; i += gridDim.x * blockDim.x)
        atomicAdd(&g_cnt[dst[i]], 1);
}

__global__ void scan1_kernel(int n) {
    __shared__ int sh[SCAN_B];
    int i = blockIdx.x * SCAN_B + threadIdx.x;
    int v = (i < n) ? g_cnt[i] : 0;
    sh[threadIdx.x] = v;
    __syncthreads();
    for (int off = 1; off < SCAN_B; off <<= 1) {
        int t = (threadIdx.x >= off) ? sh[threadIdx.x - off] : 0;
        __syncthreads();
        sh[threadIdx.x] += t;
        __syncthreads();
    }
    if (i < n) g_row[i] = sh[threadIdx.x] - v;
    if (threadIdx.x == SCAN_B - 1) g_bsum[blockIdx.x] = sh[SCAN_B - 1];
}

__global__ void scan2_kernel(int nb, int n) {
    __shared__ int sh[128];
    int t = threadIdx.x;
    int v = (t < nb) ? g_bsum[t] : 0;
    sh[t] = v;
    __syncthreads();
    for (int off = 1; off < 128; off <<= 1) {
        int u = (t >= off) ? sh[t - off] : 0;
        __syncthreads();
        sh[t] += u;
        __syncthreads();
    }
    if (t < nb) g_bsum[t] = sh[t] - v;
    if (t == 127) g_row[n] = sh[127];
}

__global__ void scan3_kernel(int n) {
    for (int i = blockIdx.x * blockDim.x + threadIdx.x; i < n; i += gridDim.x * blockDim.x) {
        int r = g_row[i] + g_bsum[i >> 10];
        g_row[i] = r;
        g_cur[i] = r;
    }
}

__global__ void scatter_kernel(const int* __restrict__ src, const int* __restrict__ dst, int E) {
    for (int i = blockIdx.x * blockDim.x + threadIdx.x; i < E; i += gridDim.x * blockDim.x) {
        int p = atomicAdd(&g_cur[dst[i]], 1);
        g_csrc[p] = src[i];
    }
}

// ---------------------------------------------------------------------------
// Layer-1 transform: h = x @ W1 (IN=9) + attention dots. One warp/node.
// Writes bf16 h; dots computed in fp32 BEFORE rounding.
__global__ void transform1_kernel(const float* __restrict__ x, const float* __restrict__ W,
                                  const float* __restrict__ atts, const float* __restrict__ attd,
                                  int n) {
    int node = (blockIdx.x * blockDim.x + threadIdx.x) >> 5;
    int lane = threadIdx.x & 31;
    if (node >= n) return;
    float xv = (lane < 9) ? x[(size_t)node * 9 + lane] : 0.f;
    float4 acc = make_float4(0.f, 0.f, 0.f, 0.f);
#pragma unroll
    for (int k = 0; k < 9; k++) {
        float xk = __shfl_sync(0xffffffffu, xv, k);
        float4 w = *(const float4*)(W + k * HID + lane * 4);
        acc.x = fmaf(xk, w.x, acc.x);
        acc.y = fmaf(xk, w.y, acc.y);
        acc.z = fmaf(xk, w.z, acc.z);
        acc.w = fmaf(xk, w.w, acc.w);
    }
    g_hb[(size_t)node * 32 + lane] = pack4bf(acc.x, acc.y, acc.z, acc.w);
    float4 s4 = *(const float4*)(atts + lane * 4);
    float4 d4 = *(const float4*)(attd + lane * 4);
    float ps = acc.x * s4.x + acc.y * s4.y + acc.z * s4.z + acc.w * s4.w;
    float pd = acc.x * d4.x + acc.y * d4.y + acc.z * d4.z + acc.w * d4.w;
#pragma unroll
    for (int off = 16; off >= 1; off >>= 1) {
        ps += __shfl_xor_sync(0xffffffffu, ps, off);
        pd += __shfl_xor_sync(0xffffffffu, pd, off);
    }
    if (lane == 0) { g_as[node] = ps; g_ad[node] = pd; }
}

// ---------------------------------------------------------------------------
// Dst-centric aggregation, online softmax, one warp per dst. bf16 gathers.
template <bool RELU>
__global__ void aggregate_kernel(const float* __restrict__ bias, int n) {
    int node = (blockIdx.x * blockDim.x + threadIdx.x) >> 5;
    int lane = threadIdx.x & 31;
    if (node >= n) return;
    int start = g_row[node], end = g_row[node + 1];
    float ad = g_ad[node];
    float m = -INFINITY, s = 0.f;
    float4 acc = make_float4(0.f, 0.f, 0.f, 0.f);
    for (int base = start; base < end; base += 32) {
        int nloc = min(32, end - base);
        int srcl = 0;
        float al = 0.f;
        if (lane < nloc) {
            srcl = g_csrc[base + lane];
            float a = g_as[srcl] + ad;
            al = (a >= 0.f) ? a : 0.2f * a;   // leaky_relu(., 0.2)
        }
#pragma unroll 4
        for (int t = 0; t < nloc; ++t) {
            int sidx = __shfl_sync(0xffffffffu, srcl, t);
            float alpha = __shfl_sync(0xffffffffu, al, t);
            float4 hv = unpack4bf(g_hb[(size_t)sidx * 32 + lane]);
            if (alpha <= m) {
                float w = __expf(alpha - m);
                s += w;
                acc.x = fmaf(w, hv.x, acc.x);
                acc.y = fmaf(w, hv.y, acc.y);
                acc.z = fmaf(w, hv.z, acc.z);
                acc.w = fmaf(w, hv.w, acc.w);
            } else {
                float sc = __expf(m - alpha);   // 0 on first edge (m=-inf)
                s = fmaf(s, sc, 1.f);
                acc.x = fmaf(acc.x, sc, hv.x);
                acc.y = fmaf(acc.y, sc, hv.y);
                acc.z = fmaf(acc.z, sc, hv.z);
                acc.w = fmaf(acc.w, sc, hv.w);
                m = alpha;
            }
        }
    }
    float inv = 1.f / (s + 1e-16f);
    float4 b = *(const float4*)(bias + lane * 4);
    float4 o;
    o.x = fmaf(acc.x, inv, b.x);
    o.y = fmaf(acc.y, inv, b.y);
    o.z = fmaf(acc.z, inv, b.z);
    o.w = fmaf(acc.w, inv, b.w);
    if (RELU) {
        o.x = fmaxf(o.x, 0.f); o.y = fmaxf(o.y, 0.f);
        o.z = fmaxf(o.z, 0.f); o.w = fmaxf(o.w, 0.f);
    }
    *(float4*)(g_acc + (size_t)node * HID + lane * 4) = o;
}

// ---------------------------------------------------------------------------
// h2 = g_acc[M,128] @ W2[128,128] (fp32 math), writes bf16 h2 + attention
// dots fused in the epilogue (dots from fp32 values). BM=64, BN=128, BK=16.
__global__ __launch_bounds__(256) void gemm128_att_kernel(const float* __restrict__ B,
                                                          const float* __restrict__ atts,
                                                          const float* __restrict__ attd,
                                                          int M) {
    __shared__ float As[16][64];
    __shared__ float Bs[16][128];
    int tid = threadIdx.x;
    int tx = tid & 31;   // N groups of 4
    int ty = tid >> 5;   // M groups of 8 (== warp id)
    int base = blockIdx.x * 64;
    float acc[8][4];
#pragma unroll
    for (int i = 0; i < 8; i++)
#pragma unroll
        for (int j = 0; j < 4; j++) acc[i][j] = 0.f;

    int am = tid >> 2;
    int ak = (tid & 3) * 4;
    for (int k0 = 0; k0 < 128; k0 += 16) {
        float4 av = make_float4(0.f, 0.f, 0.f, 0.f);
        if (base + am < M)
            av = *(const float4*)(g_acc + (size_t)(base + am) * 128 + k0 + ak);
        As[ak + 0][am] = av.x;
        As[ak + 1][am] = av.y;
        As[ak + 2][am] = av.z;
        As[ak + 3][am] = av.w;
#pragma unroll
        for (int r = 0; r < 2; r++) {
            int f = tid + r * 256;
            int bk = f >> 5, bn = (f & 31) * 4;
            *(float4*)&Bs[bk][bn] = *(const float4*)(B + (size_t)(k0 + bk) * 128 + bn);
        }
        __syncthreads();
#pragma unroll
        for (int k = 0; k < 16; k++) {
            float4 aa = *(const float4*)&As[k][ty * 8];
            float4 ab = *(const float4*)&As[k][ty * 8 + 4];
            float4 bv = *(const float4*)&Bs[k][tx * 4];
            float a[8] = {aa.x, aa.y, aa.z, aa.w, ab.x, ab.y, ab.z, ab.w};
            float b[4] = {bv.x, bv.y, bv.z, bv.w};
#pragma unroll
            for (int i = 0; i < 8; i++)
#pragma unroll
                for (int j = 0; j < 4; j++) acc[i][j] = fmaf(a[i], b[j], acc[i][j]);
        }
        __syncthreads();
    }

    // epilogue: bf16 store + fused attention dots (row lanes are one warp)
    float4 s4 = *(const float4*)(atts + tx * 4);
    float4 d4 = *(const float4*)(attd + tx * 4);
#pragma unroll
    for (int i = 0; i < 8; i++) {
        int mrow = base + ty * 8 + i;
        float ps = acc[i][0] * s4.x + acc[i][1] * s4.y + acc[i][2] * s4.z + acc[i][3] * s4.w;
        float pd = acc[i][0] * d4.x + acc[i][1] * d4.y + acc[i][2] * d4.z + acc[i][3] * d4.w;
#pragma unroll
        for (int off = 16; off >= 1; off >>= 1) {
            ps += __shfl_xor_sync(0xffffffffu, ps, off);
            pd += __shfl_xor_sync(0xffffffffu, pd, off);
        }
        if (mrow < M) {
            if (tx == 0) { g_as[mrow] = ps; g_ad[mrow] = pd; }
            g_hb[(size_t)mrow * 32 + tx] = pack4bf(acc[i][0], acc[i][1], acc[i][2], acc[i][3]);
        }
    }
}

// ---------------------------------------------------------------------------
// Mean pool by sorted batch id + classifier + log_softmax. One block/graph.
__global__ __launch_bounds__(512) void pool_kernel(const int* __restrict__ batch,
                                                   const float* __restrict__ Wc,
                                                   const float* __restrict__ bc,
                                                   float* __restrict__ out, int N) {
    int g = blockIdx.x;
    int t = threadIdx.x;
    int c = t & 127;
    int part = t >> 7;
    int lo = 0, hi = N;
    while (lo < hi) { int mid = (lo + hi) >> 1; if (batch[mid] < g) lo = mid + 1; else hi = mid; }
    int start = lo;
    hi = N;
    while (lo < hi) { int mid = (lo + hi) >> 1; if (batch[mid] < g + 1) lo = mid + 1; else hi = mid; }
    int end = lo;

    float sum = 0.f;
    for (int nd = start + part; nd < end; nd += 4) sum += g_acc[(size_t)nd * HID + c];
    __shared__ float sh[512];
    sh[t] = sum;
    __syncthreads();
    if (t < 128) {
        float s = sh[t] + sh[t + 128] + sh[t + 256] + sh[t + 384];
        float cnt = (float)(end - start);
        if (cnt < 1.f) cnt = 1.f;
        float p = s / cnt;
        sh[t] = p * Wc[c * 2 + 0];
        sh[t + 128] = p * Wc[c * 2 + 1];
    }
    __syncthreads();
    for (int off = 64; off >= 1; off >>= 1) {
        if (t < off) { sh[t] += sh[t + off]; sh[128 + t] += sh[128 + t + off]; }
        __syncthreads();
    }
    if (t == 0) {
        float l0 = sh[0] + bc[0];
        float l1 = sh[128] + bc[1];
        float mx = fmaxf(l0, l1);
        float lse = mx + logf(expf(l0 - mx) + expf(l1 - mx));
        out[g * 2 + 0] = l0 - lse;
        out[g * 2 + 1] = l1 - lse;
    }
}

// ---------------------------------------------------------------------------
static void build_csr(const int* ei, int E, int N) {
    const int* src = ei;
    const int* dst = ei + E;
    int nb_scan = (N + SCAN_B - 1) / SCAN_B;
    zero_cnt_kernel<<<(N + 255) / 256, 256>>>(N);
    hist_kernel<<<(E + 255) / 256, 256>>>(dst, E);
    scan1_kernel<<<nb_scan, SCAN_B>>>(N);
    scan2_kernel<<<1, 128>>>(nb_scan, N);
    scan3_kernel<<<(N + 255) / 256, 256>>>(N);
    scatter_kernel<<<(E + 255) / 256, 256>>>(src, dst, E);
}

extern "C" void kernel_launch(void* const* d_in, const int* in_sizes, int n_in,
                              void* d_out, int out_size) {
    const float* x      = (const float*)d_in[0];
    const int*   ei_s   = (const int*)d_in[1];
    const int*   ei_t   = (const int*)d_in[3];
    const int*   batch  = (const int*)d_in[5];
    const float* W1     = (const float*)d_in[6];
    const float* atts1  = (const float*)d_in[7];
    const float* attd1  = (const float*)d_in[8];
    const float* b1     = (const float*)d_in[9];
    const float* W2     = (const float*)d_in[10];
    const float* atts2  = (const float*)d_in[11];
    const float* attd2  = (const float*)d_in[12];
    const float* b2     = (const float*)d_in[13];
    const float* Wc     = (const float*)d_in[14];
    const float* bc     = (const float*)d_in[15];
    float* out = (float*)d_out;

    const int N = in_sizes[0] / 9;
    const int E = in_sizes[1] / 2;
    const int G = out_size / 2;

    int warp_blocks = (N * 32 + 255) / 256;

    // ---- layer 1 (spatial) ----
    transform1_kernel<<<warp_blocks, 256>>>(x, W1, atts1, attd1, N);
    build_csr(ei_s, E, N);
    aggregate_kernel<true><<<warp_blocks, 256>>>(b1, N);

    // ---- layer 2 (temporal) ----
    gemm128_att_kernel<<<(N + 63) / 64, 256>>>(W2, atts2, attd2, N);
    build_csr(ei_t, E, N);
    aggregate_kernel<false><<<warp_blocks, 256>>>(b2, N);

    // ---- pool + classify + log_softmax ----
    pool_kernel<<<G, 512>>>(batch, Wc, bc, out, N);
}

// round 4
// speedup vs baseline: 1.0278x; 1.0269x over previous
#include <cuda_runtime.h>
#include <cuda_bf16.h>
#include <math.h>
#include <stdint.h>

// ---------------------------------------------------------------------------
// TrajectoryGAT: 2x GATConv (heads=1) + mean pool + linear + log_softmax
//   N=100000, E=1600000/layer, HID=128, G=256, OUT=2
//
// R4 changes vs R3:
//   - GEMM inner loop uses packed fma.rn.f32x2 (2 fp32 FMA/instr, Blackwell)
//   - scan1/scan2 rebuilt as warp-shfl scans (2 barriers instead of ~20)
//   - g_cnt zeroing folded into transform1 / gemm epilogues (2 fewer launches)
// ---------------------------------------------------------------------------

#define N_NODES 100000
#define N_EDGES 1600000
#define HID 128

// ---- device scratch ----
__device__ uint2 g_hb[(size_t)N_NODES * 32];     // h in bf16: 128ch = 32 x uint2
__device__ float g_acc[(size_t)N_NODES * HID];   // aggregation output (fp32)
__device__ float g_as[N_NODES];
__device__ float g_ad[N_NODES];
__device__ int   g_cnt[N_NODES];
__device__ int   g_row[N_NODES + 1];
__device__ int   g_cur[N_NODES];
__device__ int   g_csrc[N_EDGES];
__device__ int   g_bsum[1024];

// ---- packed f32x2 helpers (sm_100+) ----
#define FMA_F32X2(d, a, b, c) \
    asm("fma.rn.f32x2 %0, %1, %2, %3;" : "=l"(d) : "l"(a), "l"(b), "l"(c))
#define PACKF2(d, lo, hi) \
    asm("mov.b64 %0, {%1, %2};" : "=l"(d) : "f"(lo), "f"(hi))
#define UNPACKF2(lo, hi, v) \
    asm("mov.b64 {%0, %1}, %2;" : "=f"(lo), "=f"(hi) : "l"(v))

__device__ __forceinline__ uint2 pack4bf(float a, float b, float c, float d) {
    uint2 r;
    __nv_bfloat162 p0 = __float22bfloat162_rn(make_float2(a, b));
    __nv_bfloat162 p1 = __float22bfloat162_rn(make_float2(c, d));
    r.x = *(unsigned*)&p0;
    r.y = *(unsigned*)&p1;
    return r;
}

__device__ __forceinline__ float4 unpack4bf(uint2 v) {
    float2 f0 = __bfloat1622float2(*(__nv_bfloat162*)&v.x);
    float2 f1 = __bfloat1622float2(*(__nv_bfloat162*)&v.y);
    return make_float4(f0.x, f0.y, f1.x, f1.y);
}

// ---------------------------------------------------------------------------
__global__ void hist_kernel(const int* __restrict__ dst, int E) {
    for (int i = blockIdx.x * blockDim.x + threadIdx.x; i < E; i += gridDim.x * blockDim.x)
        atomicAdd(&g_cnt[dst[i]], 1);
}

// warp-shfl two-level scan, 1024 threads/block
__global__ void scan1_kernel(int n) {
    __shared__ int ws[32];
    int i = blockIdx.x * 1024 + threadIdx.x;
    int lane = threadIdx.x & 31, w = threadIdx.x >> 5;
    int v = (i < n) ? g_cnt[i] : 0;
    int x = v;
#pragma unroll
    for (int off = 1; off < 32; off <<= 1) {
        int u = __shfl_up_sync(0xffffffffu, x, off);
        if (lane >= off) x += u;
    }
    if (lane == 31) ws[w] = x;
    __syncthreads();
    if (w == 0) {
        int s = ws[lane];
        int y = s;
#pragma unroll
        for (int off = 1; off < 32; off <<= 1) {
            int u = __shfl_up_sync(0xffffffffu, y, off);
            if (lane >= off) y += u;
        }
        ws[lane] = y - s;                      // exclusive warp offsets
        if (lane == 31) g_bsum[blockIdx.x] = y; // block total
    }
    __syncthreads();
    if (i < n) g_row[i] = x - v + ws[w];        // exclusive within block
}

// scan of block sums (nb <= 128), 128 threads
__global__ void scan2_kernel(int nb, int n) {
    __shared__ int ws[4];
    int t = threadIdx.x, lane = t & 31, w = t >> 5;
    int v = (t < nb) ? g_bsum[t] : 0;
    int x = v;
#pragma unroll
    for (int off = 1; off < 32; off <<= 1) {
        int u = __shfl_up_sync(0xffffffffu, x, off);
        if (lane >= off) x += u;
    }
    if (lane == 31) ws[w] = x;
    __syncthreads();
    int add = 0;
    if (w > 0) add = ws[0];
    if (w > 1) add += ws[1];
    if (w > 2) add += ws[2];
    x += add;
    if (t < nb) g_bsum[t] = x - v;             // exclusive
    if (t == 127) g_row[n] = x;                // grand total = E
}

__global__ void scan3_kernel(int n) {
    for (int i = blockIdx.x * blockDim.x + threadIdx.x; i < n; i += gridDim.x * blockDim.x) {
        int r = g_row[i] + g_bsum[i >> 10];
        g_row[i] = r;
        g_cur[i] = r;
    }
}

__global__ void scatter_kernel(const int* __restrict__ src, const int* __restrict__ dst, int E) {
    for (int i = blockIdx.x * blockDim.x + threadIdx.x; i < E; i += gridDim.x * blockDim.x) {
        int p = atomicAdd(&g_cur[dst[i]], 1);
        g_csrc[p] = src[i];
    }
}

// ---------------------------------------------------------------------------
// Layer-1 transform: h = x @ W1 (IN=9) + attention dots + zero g_cnt.
__global__ void transform1_kernel(const float* __restrict__ x, const float* __restrict__ W,
                                  const float* __restrict__ atts, const float* __restrict__ attd,
                                  int n) {
    int node = (blockIdx.x * blockDim.x + threadIdx.x) >> 5;
    int lane = threadIdx.x & 31;
    if (node >= n) return;
    float xv = (lane < 9) ? x[(size_t)node * 9 + lane] : 0.f;
    float4 acc = make_float4(0.f, 0.f, 0.f, 0.f);
#pragma unroll
    for (int k = 0; k < 9; k++) {
        float xk = __shfl_sync(0xffffffffu, xv, k);
        float4 w = *(const float4*)(W + k * HID + lane * 4);
        acc.x = fmaf(xk, w.x, acc.x);
        acc.y = fmaf(xk, w.y, acc.y);
        acc.z = fmaf(xk, w.z, acc.z);
        acc.w = fmaf(xk, w.w, acc.w);
    }
    g_hb[(size_t)node * 32 + lane] = pack4bf(acc.x, acc.y, acc.z, acc.w);
    float4 s4 = *(const float4*)(atts + lane * 4);
    float4 d4 = *(const float4*)(attd + lane * 4);
    float ps = acc.x * s4.x + acc.y * s4.y + acc.z * s4.z + acc.w * s4.w;
    float pd = acc.x * d4.x + acc.y * d4.y + acc.z * d4.z + acc.w * d4.w;
#pragma unroll
    for (int off = 16; off >= 1; off >>= 1) {
        ps += __shfl_xor_sync(0xffffffffu, ps, off);
        pd += __shfl_xor_sync(0xffffffffu, pd, off);
    }
    if (lane == 0) { g_as[node] = ps; g_ad[node] = pd; g_cnt[node] = 0; }
}

// ---------------------------------------------------------------------------
// Dst-centric aggregation, online softmax, one warp per dst. bf16 gathers.
template <bool RELU>
__global__ void aggregate_kernel(const float* __restrict__ bias, int n) {
    int node = (blockIdx.x * blockDim.x + threadIdx.x) >> 5;
    int lane = threadIdx.x & 31;
    if (node >= n) return;
    int start = g_row[node], end = g_row[node + 1];
    float ad = g_ad[node];
    float m = -INFINITY, s = 0.f;
    float4 acc = make_float4(0.f, 0.f, 0.f, 0.f);
    for (int base = start; base < end; base += 32) {
        int nloc = min(32, end - base);
        int srcl = 0;
        float al = 0.f;
        if (lane < nloc) {
            srcl = g_csrc[base + lane];
            float a = g_as[srcl] + ad;
            al = (a >= 0.f) ? a : 0.2f * a;   // leaky_relu(., 0.2)
        }
#pragma unroll 4
        for (int t = 0; t < nloc; ++t) {
            int sidx = __shfl_sync(0xffffffffu, srcl, t);
            float alpha = __shfl_sync(0xffffffffu, al, t);
            float4 hv = unpack4bf(g_hb[(size_t)sidx * 32 + lane]);
            if (alpha <= m) {
                float w = __expf(alpha - m);
                s += w;
                acc.x = fmaf(w, hv.x, acc.x);
                acc.y = fmaf(w, hv.y, acc.y);
                acc.z = fmaf(w, hv.z, acc.z);
                acc.w = fmaf(w, hv.w, acc.w);
            } else {
                float sc = __expf(m - alpha);   // 0 on first edge (m=-inf)
                s = fmaf(s, sc, 1.f);
                acc.x = fmaf(acc.x, sc, hv.x);
                acc.y = fmaf(acc.y, sc, hv.y);
                acc.z = fmaf(acc.z, sc, hv.z);
                acc.w = fmaf(acc.w, sc, hv.w);
                m = alpha;
            }
        }
    }
    float inv = 1.f / (s + 1e-16f);
    float4 b = *(const float4*)(bias + lane * 4);
    float4 o;
    o.x = fmaf(acc.x, inv, b.x);
    o.y = fmaf(acc.y, inv, b.y);
    o.z = fmaf(acc.z, inv, b.z);
    o.w = fmaf(acc.w, inv, b.w);
    if (RELU) {
        o.x = fmaxf(o.x, 0.f); o.y = fmaxf(o.y, 0.f);
        o.z = fmaxf(o.z, 0.f); o.w = fmaxf(o.w, 0.f);
    }
    *(float4*)(g_acc + (size_t)node * HID + lane * 4) = o;
}

// ---------------------------------------------------------------------------
// h2 = g_acc[M,128] @ W2[128,128] via packed f32x2 FMA; bf16 store + fused
// attention dots + zero g_cnt in epilogue. BM=64, BN=128, BK=16, 256 thr.
__global__ __launch_bounds__(256) void gemm128_att_kernel(const float* __restrict__ B,
                                                          const float* __restrict__ atts,
                                                          const float* __restrict__ attd,
                                                          int M) {
    __shared__ float As[16][64];
    __shared__ float Bs[16][128];
    int tid = threadIdx.x;
    int tx = tid & 31;   // N groups of 4
    int ty = tid >> 5;   // M groups of 8 (== warp id)
    int base = blockIdx.x * 64;
    unsigned long long acc2[8][2];
#pragma unroll
    for (int i = 0; i < 8; i++) { acc2[i][0] = 0ull; acc2[i][1] = 0ull; }

    int am = tid >> 2;
    int ak = (tid & 3) * 4;
    for (int k0 = 0; k0 < 128; k0 += 16) {
        float4 av = make_float4(0.f, 0.f, 0.f, 0.f);
        if (base + am < M)
            av = *(const float4*)(g_acc + (size_t)(base + am) * 128 + k0 + ak);
        As[ak + 0][am] = av.x;
        As[ak + 1][am] = av.y;
        As[ak + 2][am] = av.z;
        As[ak + 3][am] = av.w;
#pragma unroll
        for (int r = 0; r < 2; r++) {
            int f = tid + r * 256;
            int bk = f >> 5, bn = (f & 31) * 4;
            *(float4*)&Bs[bk][bn] = *(const float4*)(B + (size_t)(k0 + bk) * 128 + bn);
        }
        __syncthreads();
#pragma unroll
        for (int k = 0; k < 16; k++) {
            float4 aa = *(const float4*)&As[k][ty * 8];
            float4 ab = *(const float4*)&As[k][ty * 8 + 4];
            float4 bv = *(const float4*)&Bs[k][tx * 4];
            unsigned long long b01, b23;
            PACKF2(b01, bv.x, bv.y);
            PACKF2(b23, bv.z, bv.w);
            float a[8] = {aa.x, aa.y, aa.z, aa.w, ab.x, ab.y, ab.z, ab.w};
#pragma unroll
            for (int i = 0; i < 8; i++) {
                unsigned long long ad2;
                PACKF2(ad2, a[i], a[i]);
                FMA_F32X2(acc2[i][0], ad2, b01, acc2[i][0]);
                FMA_F32X2(acc2[i][1], ad2, b23, acc2[i][1]);
            }
        }
        __syncthreads();
    }

    // epilogue: unpack, bf16 store, fused attention dots, zero g_cnt
    float4 s4 = *(const float4*)(atts + tx * 4);
    float4 d4 = *(const float4*)(attd + tx * 4);
#pragma unroll
    for (int i = 0; i < 8; i++) {
        int mrow = base + ty * 8 + i;
        float c0, c1, c2, c3;
        UNPACKF2(c0, c1, acc2[i][0]);
        UNPACKF2(c2, c3, acc2[i][1]);
        float ps = c0 * s4.x + c1 * s4.y + c2 * s4.z + c3 * s4.w;
        float pd = c0 * d4.x + c1 * d4.y + c2 * d4.z + c3 * d4.w;
#pragma unroll
        for (int off = 16; off >= 1; off >>= 1) {
            ps += __shfl_xor_sync(0xffffffffu, ps, off);
            pd += __shfl_xor_sync(0xffffffffu, pd, off);
        }
        if (mrow < M) {
            if (tx == 0) { g_as[mrow] = ps; g_ad[mrow] = pd; g_cnt[mrow] = 0; }
            g_hb[(size_t)mrow * 32 + tx] = pack4bf(c0, c1, c2, c3);
        }
    }
}

// ---------------------------------------------------------------------------
// Mean pool by sorted batch id + classifier + log_softmax. One block/graph.
__global__ __launch_bounds__(512) void pool_kernel(const int* __restrict__ batch,
                                                   const float* __restrict__ Wc,
                                                   const float* __restrict__ bc,
                                                   float* __restrict__ out, int N) {
    int g = blockIdx.x;
    int t = threadIdx.x;
    int c = t & 127;
    int part = t >> 7;
    int lo = 0, hi = N;
    while (lo < hi) { int mid = (lo + hi) >> 1; if (batch[mid] < g) lo = mid + 1; else hi = mid; }
    int start = lo;
    hi = N;
    while (lo < hi) { int mid = (lo + hi) >> 1; if (batch[mid] < g + 1) lo = mid + 1; else hi = mid; }
    int end = lo;

    float sum = 0.f;
    for (int nd = start + part; nd < end; nd += 4) sum += g_acc[(size_t)nd * HID + c];
    __shared__ float sh[512];
    sh[t] = sum;
    __syncthreads();
    if (t < 128) {
        float s = sh[t] + sh[t + 128] + sh[t + 256] + sh[t + 384];
        float cnt = (float)(end - start);
        if (cnt < 1.f) cnt = 1.f;
        float p = s / cnt;
        sh[t] = p * Wc[c * 2 + 0];
        sh[t + 128] = p * Wc[c * 2 + 1];
    }
    __syncthreads();
    for (int off = 64; off >= 1; off >>= 1) {
        if (t < off) { sh[t] += sh[t + off]; sh[128 + t] += sh[128 + t + off]; }
        __syncthreads();
    }
    if (t == 0) {
        float l0 = sh[0] + bc[0];
        float l1 = sh[128] + bc[1];
        float mx = fmaxf(l0, l1);
        float lse = mx + logf(expf(l0 - mx) + expf(l1 - mx));
        out[g * 2 + 0] = l0 - lse;
        out[g * 2 + 1] = l1 - lse;
    }
}

// ---------------------------------------------------------------------------
// NOTE: g_cnt must already be zeroed by the preceding kernel's epilogue.
static void build_csr(const int* ei, int E, int N) {
    const int* src = ei;
    const int* dst = ei + E;
    int nb_scan = (N + 1023) / 1024;
    hist_kernel<<<(E + 255) / 256, 256>>>(dst, E);
    scan1_kernel<<<nb_scan, 1024>>>(N);
    scan2_kernel<<<1, 128>>>(nb_scan, N);
    scan3_kernel<<<(N + 255) / 256, 256>>>(N);
    scatter_kernel<<<(E + 255) / 256, 256>>>(src, dst, E);
}

extern "C" void kernel_launch(void* const* d_in, const int* in_sizes, int n_in,
                              void* d_out, int out_size) {
    const float* x      = (const float*)d_in[0];
    const int*   ei_s   = (const int*)d_in[1];
    const int*   ei_t   = (const int*)d_in[3];
    const int*   batch  = (const int*)d_in[5];
    const float* W1     = (const float*)d_in[6];
    const float* atts1  = (const float*)d_in[7];
    const float* attd1  = (const float*)d_in[8];
    const float* b1     = (const float*)d_in[9];
    const float* W2     = (const float*)d_in[10];
    const float* atts2  = (const float*)d_in[11];
    const float* attd2  = (const float*)d_in[12];
    const float* b2     = (const float*)d_in[13];
    const float* Wc     = (const float*)d_in[14];
    const float* bc     = (const float*)d_in[15];
    float* out = (float*)d_out;

    const int N = in_sizes[0] / 9;
    const int E = in_sizes[1] / 2;
    const int G = out_size / 2;

    int warp_blocks = (N * 32 + 255) / 256;

    // ---- layer 1 (spatial) ----  (transform1 also zeroes g_cnt)
    transform1_kernel<<<warp_blocks, 256>>>(x, W1, atts1, attd1, N);
    build_csr(ei_s, E, N);
    aggregate_kernel<true><<<warp_blocks, 256>>>(b1, N);

    // ---- layer 2 (temporal) ----  (gemm epilogue zeroes g_cnt)
    gemm128_att_kernel<<<(N + 63) / 64, 256>>>(W2, atts2, attd2, N);
    build_csr(ei_t, E, N);
    aggregate_kernel<false><<<warp_blocks, 256>>>(b2, N);

    // ---- pool + classify + log_softmax ----
    pool_kernel<<<G, 512>>>(batch, Wc, bc, out, N);
}

// round 5
// speedup vs baseline: 1.3024x; 1.2672x over previous
#include <cuda_runtime.h>
#include <cuda_bf16.h>
#include <math.h>
#include <stdint.h>

// ---------------------------------------------------------------------------
// TrajectoryGAT: 2x GATConv (heads=1) + mean pool + linear + log_softmax
//   N=100000, E=1600000/layer, HID=128, G=256, OUT=2
//
// R5 changes vs R4:
//   - both CSRs built together (concat arrays): 10 CSR launches -> 5
//   - init kernel fuses cnt zeroing + W2->bf16 convert
//   - aggregate: two-phase softmax (true max, lane-parallel exp, slim loop)
//   - layer-2 GEMM on tensor cores (bf16 mma.sync.m16n8k16, fp32 accum)
//   - 15 launches -> 11
// ---------------------------------------------------------------------------

#define NN 100000
#define EE 1600000
#define HID 128

// ---- device scratch ----
__device__ uint2    g_hb[(size_t)NN * 32];    // h (bf16) for gathers, both layers
__device__ uint2    g_ab[(size_t)NN * 32];    // layer-1 out (bf16) = GEMM A
__device__ float    g_acc[(size_t)NN * HID];  // layer-2 out (fp32) for pool
__device__ float    g_as[NN];
__device__ float    g_ad[NN];
__device__ int      g_cnt[2 * NN];
__device__ int      g_rowc[2 * NN + 1];       // concat exclusive scan
__device__ int      g_cur[2 * NN];
__device__ int      g_csrc[2 * EE];           // src ids grouped by (layer,dst)
__device__ int      g_bsum[256];
__device__ unsigned g_w2b[64 * HID];          // W2 in bf16x2, row-major [k][n]

__device__ __forceinline__ uint2 pack4bf(float a, float b, float c, float d) {
    uint2 r;
    __nv_bfloat162 p0 = __float22bfloat162_rn(make_float2(a, b));
    __nv_bfloat162 p1 = __float22bfloat162_rn(make_float2(c, d));
    r.x = *(unsigned*)&p0;
    r.y = *(unsigned*)&p1;
    return r;
}

__device__ __forceinline__ float4 unpack4bf(uint2 v) {
    float2 f0 = __bfloat1622float2(*(__nv_bfloat162*)&v.x);
    float2 f1 = __bfloat1622float2(*(__nv_bfloat162*)&v.y);
    return make_float4(f0.x, f0.y, f1.x, f1.y);
}

// ---------------------------------------------------------------------------
// init: zero both histograms + convert W2 to bf16
__global__ void init_kernel(const float* __restrict__ W2) {
    int i = blockIdx.x * 256 + threadIdx.x;
    if (i < 2 * NN) g_cnt[i] = 0;
    if (i < 64 * HID) {
        float2 v = *(const float2*)(W2 + i * 2);
        __nv_bfloat162 p = __float22bfloat162_rn(v);
        g_w2b[i] = *(unsigned*)&p;
    }
}

// both histograms in one launch
__global__ void hist_kernel(const int* __restrict__ dst_s, const int* __restrict__ dst_t, int E) {
    int i = blockIdx.x * 256 + threadIdx.x;
    if (i < E) atomicAdd(&g_cnt[dst_s[i]], 1);
    else if (i < 2 * E) atomicAdd(&g_cnt[NN + dst_t[i - E]], 1);
}

// warp-shfl two-level scan over concat cnt (2N), 1024 thr/block
__global__ void scan1_kernel(int n2) {
    __shared__ int ws[32];
    int i = blockIdx.x * 1024 + threadIdx.x;
    int lane = threadIdx.x & 31, w = threadIdx.x >> 5;
    int v = (i < n2) ? g_cnt[i] : 0;
    int x = v;
#pragma unroll
    for (int off = 1; off < 32; off <<= 1) {
        int u = __shfl_up_sync(0xffffffffu, x, off);
        if (lane >= off) x += u;
    }
    if (lane == 31) ws[w] = x;
    __syncthreads();
    if (w == 0) {
        int s = ws[lane];
        int y = s;
#pragma unroll
        for (int off = 1; off < 32; off <<= 1) {
            int u = __shfl_up_sync(0xffffffffu, y, off);
            if (lane >= off) y += u;
        }
        ws[lane] = y - s;
        if (lane == 31) g_bsum[blockIdx.x] = y;
    }
    __syncthreads();
    if (i < n2) g_rowc[i] = x - v + ws[w];
}

// scan of block sums (nb <= 256), 256 threads
__global__ void scan2_kernel(int nb, int n2) {
    __shared__ int ws[8];
    int t = threadIdx.x, lane = t & 31, w = t >> 5;
    int v = (t < nb) ? g_bsum[t] : 0;
    int x = v;
#pragma unroll
    for (int off = 1; off < 32; off <<= 1) {
        int u = __shfl_up_sync(0xffffffffu, x, off);
        if (lane >= off) x += u;
    }
    if (lane == 31) ws[w] = x;
    __syncthreads();
    int add = 0;
#pragma unroll
    for (int j = 0; j < 8; ++j)
        if (j < w) add += ws[j];
    x += add;
    if (t < nb) g_bsum[t] = x - v;
    if (t == 255) g_rowc[n2] = x;   // grand total = 2E
}

__global__ void scan3_kernel(int n2) {
    for (int i = blockIdx.x * blockDim.x + threadIdx.x; i < n2; i += gridDim.x * blockDim.x) {
        int r = g_rowc[i] + g_bsum[i >> 10];
        g_rowc[i] = r;
        g_cur[i] = r;
    }
}

// both scatters in one launch; layer-2 positions land at [E,2E) automatically
__global__ void scatter_kernel(const int* __restrict__ src_s, const int* __restrict__ dst_s,
                               const int* __restrict__ src_t, const int* __restrict__ dst_t, int E) {
    int i = blockIdx.x * 256 + threadIdx.x;
    int s, slot;
    if (i < E)            { s = src_s[i];     slot = dst_s[i]; }
    else if (i < 2 * E)   { s = src_t[i - E]; slot = NN + dst_t[i - E]; }
    else return;
    int p = atomicAdd(&g_cur[slot], 1);
    g_csrc[p] = s;
}

// ---------------------------------------------------------------------------
// Layer-1 transform: h = x @ W1 (IN=9) + attention dots. One warp/node.
__global__ void transform1_kernel(const float* __restrict__ x, const float* __restrict__ W,
                                  const float* __restrict__ atts, const float* __restrict__ attd,
                                  int n) {
    int node = (blockIdx.x * blockDim.x + threadIdx.x) >> 5;
    int lane = threadIdx.x & 31;
    if (node >= n) return;
    float xv = (lane < 9) ? x[(size_t)node * 9 + lane] : 0.f;
    float4 acc = make_float4(0.f, 0.f, 0.f, 0.f);
#pragma unroll
    for (int k = 0; k < 9; k++) {
        float xk = __shfl_sync(0xffffffffu, xv, k);
        float4 w = *(const float4*)(W + k * HID + lane * 4);
        acc.x = fmaf(xk, w.x, acc.x);
        acc.y = fmaf(xk, w.y, acc.y);
        acc.z = fmaf(xk, w.z, acc.z);
        acc.w = fmaf(xk, w.w, acc.w);
    }
    g_hb[(size_t)node * 32 + lane] = pack4bf(acc.x, acc.y, acc.z, acc.w);
    float4 s4 = *(const float4*)(atts + lane * 4);
    float4 d4 = *(const float4*)(attd + lane * 4);
    float ps = acc.x * s4.x + acc.y * s4.y + acc.z * s4.z + acc.w * s4.w;
    float pd = acc.x * d4.x + acc.y * d4.y + acc.z * d4.z + acc.w * d4.w;
#pragma unroll
    for (int off = 16; off >= 1; off >>= 1) {
        ps += __shfl_xor_sync(0xffffffffu, ps, off);
        pd += __shfl_xor_sync(0xffffffffu, pd, off);
    }
    if (lane == 0) { g_as[node] = ps; g_ad[node] = pd; }
}

// ---------------------------------------------------------------------------
// Two-phase aggregation. One warp per dst node.
// LAYER=0: relu, write bf16 to g_ab. LAYER=1: write fp32 to g_acc.
template <int LAYER>
__global__ void aggregate_kernel(const float* __restrict__ bias, int n) {
    int node = (blockIdx.x * blockDim.x + threadIdx.x) >> 5;
    int lane = threadIdx.x & 31;
    if (node >= n) return;
    const int* rowb = g_rowc + LAYER * NN;
    int start = rowb[node], end = rowb[node + 1];
    float4 b = *(const float4*)(bias + lane * 4);

    if (start == end) {
        float4 o = b;
        if (LAYER == 0) {
            o.x = fmaxf(o.x, 0.f); o.y = fmaxf(o.y, 0.f);
            o.z = fmaxf(o.z, 0.f); o.w = fmaxf(o.w, 0.f);
            g_ab[(size_t)node * 32 + lane] = pack4bf(o.x, o.y, o.z, o.w);
        } else {
            *(float4*)(g_acc + (size_t)node * HID + lane * 4) = o;
        }
        return;
    }

    float ad = g_ad[node];
    // phase A: true max over edges (lane-parallel)
    float m = -INFINITY;
    for (int bi = start + lane; bi < end; bi += 32) {
        int s = g_csrc[bi];
        float a = g_as[s] + ad;
        a = (a >= 0.f) ? a : 0.2f * a;
        m = fmaxf(m, a);
    }
#pragma unroll
    for (int off = 16; off >= 1; off >>= 1)
        m = fmaxf(m, __shfl_xor_sync(0xffffffffu, m, off));

    // phase B: lane-parallel exp, slim broadcast accumulate
    float ssum = 0.f;
    float4 acc = make_float4(0.f, 0.f, 0.f, 0.f);
    for (int basei = start; basei < end; basei += 32) {
        int nloc = min(32, end - basei);
        int srcl = 0;
        float wv = 0.f;
        if (lane < nloc) {
            srcl = g_csrc[basei + lane];
            float a = g_as[srcl] + ad;
            a = (a >= 0.f) ? a : 0.2f * a;
            wv = __expf(a - m);
        }
        ssum += wv;
#pragma unroll 4
        for (int t = 0; t < nloc; ++t) {
            int sidx = __shfl_sync(0xffffffffu, srcl, t);
            float wt = __shfl_sync(0xffffffffu, wv, t);
            float4 hv = unpack4bf(g_hb[(size_t)sidx * 32 + lane]);
            acc.x = fmaf(wt, hv.x, acc.x);
            acc.y = fmaf(wt, hv.y, acc.y);
            acc.z = fmaf(wt, hv.z, acc.z);
            acc.w = fmaf(wt, hv.w, acc.w);
        }
    }
#pragma unroll
    for (int off = 16; off >= 1; off >>= 1)
        ssum += __shfl_xor_sync(0xffffffffu, ssum, off);

    float inv = 1.f / (ssum + 1e-16f);
    float4 o;
    o.x = fmaf(acc.x, inv, b.x);
    o.y = fmaf(acc.y, inv, b.y);
    o.z = fmaf(acc.z, inv, b.z);
    o.w = fmaf(acc.w, inv, b.w);
    if (LAYER == 0) {
        o.x = fmaxf(o.x, 0.f); o.y = fmaxf(o.y, 0.f);
        o.z = fmaxf(o.z, 0.f); o.w = fmaxf(o.w, 0.f);
        g_ab[(size_t)node * 32 + lane] = pack4bf(o.x, o.y, o.z, o.w);
    } else {
        *(float4*)(g_acc + (size_t)node * HID + lane * 4) = o;
    }
}

// ---------------------------------------------------------------------------
// Tensor-core GEMM: h2[M,128] = g_ab[M,128](bf16) @ W2bf[128,128], fp32 accum.
// BM=128, 256 thr (8 warps x 16 rows), K staged in 2 chunks of 64.
// Epilogue: bf16 store to g_hb + fused attention dots.
__global__ __launch_bounds__(256) void gemm_mma_kernel(const float* __restrict__ atts,
                                                       const float* __restrict__ attd, int M) {
    __shared__ __nv_bfloat16 As[128 * 72];   // 128 rows x 64 (+8 pad), 144 B/row
    __shared__ __nv_bfloat16 Bs[64 * 136];   // 64 k-rows x 128 (+8 pad), 272 B/row
    int tid = threadIdx.x;
    int lane = tid & 31, w = tid >> 5;
    int m0 = blockIdx.x * 128;
    float c[16][4];
#pragma unroll
    for (int i = 0; i < 16; i++)
#pragma unroll
        for (int j = 0; j < 4; j++) c[i][j] = 0.f;

    const char* abase = (const char*)g_ab;
    const char* bbase = (const char*)g_w2b;
    int grp = lane >> 3;
    int mw = w * 16;

    for (int ks = 0; ks < 2; ++ks) {
        // stage A chunk: rows 0..127, k cols ks*64..+63 (128 B per row)
#pragma unroll
        for (int it = 0; it < 4; ++it) {
            int idx = tid + it * 256;            // 0..1023
            int r = idx >> 3, c8 = idx & 7;
            uint4 v = make_uint4(0, 0, 0, 0);
            if (m0 + r < M)
                v = *(const uint4*)(abase + (size_t)(m0 + r) * 256 + ks * 128 + c8 * 16);
            *(uint4*)((char*)As + r * 144 + c8 * 16) = v;
        }
        // stage B chunk: k rows ks*64..+63, 128 n (256 B per row)
#pragma unroll
        for (int it = 0; it < 4; ++it) {
            int idx = tid + it * 256;
            int r = idx >> 4, c16 = idx & 15;
            uint4 v = *(const uint4*)(bbase + (size_t)(ks * 64 + r) * 256 + c16 * 16);
            *(uint4*)((char*)Bs + r * 272 + c16 * 16) = v;
        }
        __syncthreads();

#pragma unroll
        for (int kk = 0; kk < 64; kk += 16) {
            // A fragment (m16 x k16)
            int arow = mw + (lane & 7) + (grp & 1) * 8;
            int acol = kk + (grp >> 1) * 8;
            uint32_t aaddr = (uint32_t)__cvta_generic_to_shared(As) + arow * 144 + acol * 2;
            uint32_t a0, a1, a2, a3;
            asm volatile("ldmatrix.sync.aligned.m8n8.x4.shared.b16 {%0,%1,%2,%3}, [%4];"
                         : "=r"(a0), "=r"(a1), "=r"(a2), "=r"(a3) : "r"(aaddr));
#pragma unroll
            for (int np = 0; np < 8; ++np) {
                int brow = kk + (lane & 7) + (grp & 1) * 8;
                int bcol = np * 16 + (grp >> 1) * 8;
                uint32_t baddr = (uint32_t)__cvta_generic_to_shared(Bs) + brow * 272 + bcol * 2;
                uint32_t b0, b1, b2, b3;
                asm volatile("ldmatrix.sync.aligned.m8n8.x4.trans.shared.b16 {%0,%1,%2,%3}, [%4];"
                             : "=r"(b0), "=r"(b1), "=r"(b2), "=r"(b3) : "r"(baddr));
                asm volatile("mma.sync.aligned.m16n8k16.row.col.f32.bf16.bf16.f32 "
                             "{%0,%1,%2,%3}, {%4,%5,%6,%7}, {%8,%9}, {%0,%1,%2,%3};"
                             : "+f"(c[2 * np][0]), "+f"(c[2 * np][1]),
                               "+f"(c[2 * np][2]), "+f"(c[2 * np][3])
                             : "r"(a0), "r"(a1), "r"(a2), "r"(a3), "r"(b0), "r"(b1));
                asm volatile("mma.sync.aligned.m16n8k16.row.col.f32.bf16.bf16.f32 "
                             "{%0,%1,%2,%3}, {%4,%5,%6,%7}, {%8,%9}, {%0,%1,%2,%3};"
                             : "+f"(c[2 * np + 1][0]), "+f"(c[2 * np + 1][1]),
                               "+f"(c[2 * np + 1][2]), "+f"(c[2 * np + 1][3])
                             : "r"(a0), "r"(a1), "r"(a2), "r"(a3), "r"(b2), "r"(b3));
            }
        }
        __syncthreads();
    }

    // epilogue: C frag rows r=lane/4 (c0,c1) and r+8 (c2,c3); cols nt*8+q*2
    int r = lane >> 2, q = lane & 3;
    int row1 = m0 + mw + r, row2 = row1 + 8;
    unsigned* hb32 = (unsigned*)g_hb;
    float ps1 = 0.f, pd1 = 0.f, ps2 = 0.f, pd2 = 0.f;
#pragma unroll
    for (int nt = 0; nt < 16; ++nt) {
        int col = nt * 8 + q * 2;
        float2 sa = *(const float2*)(atts + col);
        float2 da = *(const float2*)(attd + col);
        ps1 += c[nt][0] * sa.x + c[nt][1] * sa.y;
        pd1 += c[nt][0] * da.x + c[nt][1] * da.y;
        ps2 += c[nt][2] * sa.x + c[nt][3] * sa.y;
        pd2 += c[nt][2] * da.x + c[nt][3] * da.y;
        if (row1 < M) {
            __nv_bfloat162 p = __float22bfloat162_rn(make_float2(c[nt][0], c[nt][1]));
            hb32[(size_t)row1 * 64 + nt * 4 + q] = *(unsigned*)&p;
        }
        if (row2 < M) {
            __nv_bfloat162 p = __float22bfloat162_rn(make_float2(c[nt][2], c[nt][3]));
            hb32[(size_t)row2 * 64 + nt * 4 + q] = *(unsigned*)&p;
        }
    }
#pragma unroll
    for (int off = 1; off <= 2; off <<= 1) {
        ps1 += __shfl_xor_sync(0xffffffffu, ps1, off);
        pd1 += __shfl_xor_sync(0xffffffffu, pd1, off);
        ps2 += __shfl_xor_sync(0xffffffffu, ps2, off);
        pd2 += __shfl_xor_sync(0xffffffffu, pd2, off);
    }
    if (q == 0) {
        if (row1 < M) { g_as[row1] = ps1; g_ad[row1] = pd1; }
        if (row2 < M) { g_as[row2] = ps2; g_ad[row2] = pd2; }
    }
}

// ---------------------------------------------------------------------------
// Mean pool by sorted batch id + classifier + log_softmax. One block/graph.
__global__ __launch_bounds__(512) void pool_kernel(const int* __restrict__ batch,
                                                   const float* __restrict__ Wc,
                                                   const float* __restrict__ bc,
                                                   float* __restrict__ out, int N) {
    int g = blockIdx.x;
    int t = threadIdx.x;
    int c = t & 127;
    int part = t >> 7;
    int lo = 0, hi = N;
    while (lo < hi) { int mid = (lo + hi) >> 1; if (batch[mid] < g) lo = mid + 1; else hi = mid; }
    int start = lo;
    hi = N;
    while (lo < hi) { int mid = (lo + hi) >> 1; if (batch[mid] < g + 1) lo = mid + 1; else hi = mid; }
    int end = lo;

    float sum = 0.f;
    for (int nd = start + part; nd < end; nd += 4) sum += g_acc[(size_t)nd * HID + c];
    __shared__ float sh[512];
    sh[t] = sum;
    __syncthreads();
    if (t < 128) {
        float s = sh[t] + sh[t + 128] + sh[t + 256] + sh[t + 384];
        float cnt = (float)(end - start);
        if (cnt < 1.f) cnt = 1.f;
        float p = s / cnt;
        sh[t] = p * Wc[c * 2 + 0];
        sh[t + 128] = p * Wc[c * 2 + 1];
    }
    __syncthreads();
    for (int off = 64; off >= 1; off >>= 1) {
        if (t < off) { sh[t] += sh[t + off]; sh[128 + t] += sh[128 + t + off]; }
        __syncthreads();
    }
    if (t == 0) {
        float l0 = sh[0] + bc[0];
        float l1 = sh[128] + bc[1];
        float mx = fmaxf(l0, l1);
        float lse = mx + logf(expf(l0 - mx) + expf(l1 - mx));
        out[g * 2 + 0] = l0 - lse;
        out[g * 2 + 1] = l1 - lse;
    }
}

// ---------------------------------------------------------------------------
extern "C" void kernel_launch(void* const* d_in, const int* in_sizes, int n_in,
                              void* d_out, int out_size) {
    const float* x      = (const float*)d_in[0];
    const int*   ei_s   = (const int*)d_in[1];
    const int*   ei_t   = (const int*)d_in[3];
    const int*   batch  = (const int*)d_in[5];
    const float* W1     = (const float*)d_in[6];
    const float* atts1  = (const float*)d_in[7];
    const float* attd1  = (const float*)d_in[8];
    const float* b1     = (const float*)d_in[9];
    const float* W2     = (const float*)d_in[10];
    const float* atts2  = (const float*)d_in[11];
    const float* attd2  = (const float*)d_in[12];
    const float* b2     = (const float*)d_in[13];
    const float* Wc     = (const float*)d_in[14];
    const float* bc     = (const float*)d_in[15];
    float* out = (float*)d_out;

    const int N = in_sizes[0] / 9;
    const int E = in_sizes[1] / 2;
    const int G = out_size / 2;
    const int n2 = 2 * N;

    int warp_blocks = (N * 32 + 255) / 256;
    int nb_scan = (n2 + 1023) / 1024;

    // ---- init + both CSR builds (5 fused launches) ----
    init_kernel<<<(n2 + 255) / 256, 256>>>(W2);
    hist_kernel<<<(2 * E + 255) / 256, 256>>>(ei_s + E, ei_t + E, E);
    scan1_kernel<<<nb_scan, 1024>>>(n2);
    scan2_kernel<<<1, 256>>>(nb_scan, n2);
    scan3_kernel<<<(n2 + 255) / 256, 256>>>(n2);
    scatter_kernel<<<(2 * E + 255) / 256, 256>>>(ei_s, ei_s + E, ei_t, ei_t + E, E);

    // ---- layer 1 (spatial) ----
    transform1_kernel<<<warp_blocks, 256>>>(x, W1, atts1, attd1, N);
    aggregate_kernel<0><<<warp_blocks, 256>>>(b1, N);

    // ---- layer 2 (temporal) ----
    gemm_mma_kernel<<<(N + 127) / 128, 256>>>(atts2, attd2, N);
    aggregate_kernel<1><<<warp_blocks, 256>>>(b2, N);

    // ---- pool + classify + log_softmax ----
    pool_kernel<<<G, 512>>>(batch, Wc, bc, out, N);
}

// round 6
// speedup vs baseline: 1.3025x; 1.0001x over previous
#include <cuda_runtime.h>
#include <cuda_bf16.h>
#include <math.h>
#include <stdint.h>

// ---------------------------------------------------------------------------
// TrajectoryGAT: 2x GATConv + mean pool + linear + log_softmax
//   N=100000, E=1600000/layer, HID=128, G=256, OUT=2
//
// R6 changes vs R5:
//   - transform1 + both histograms + W2->bf16 fused into ONE kernel (overlap)
//   - 3-kernel scan -> 1 decoupled-lookback scan (98 blocks, single wave)
//   - scatter kernel also resets cnt/flags/ticket for the next graph replay
//   - aggregate broadcast loop unroll 4 -> 8
//   - 10 launches -> 7
// ---------------------------------------------------------------------------

#define NN 100000
#define EE 1600000
#define HID 128
#define SCAN_ELEMS 2048

// ---- device scratch ----
__device__ uint2    g_hb[(size_t)NN * 32];    // h (bf16) for gathers, both layers
__device__ uint2    g_ab[(size_t)NN * 32];    // layer-1 out (bf16) = GEMM A
__device__ float    g_acc[(size_t)NN * HID];  // layer-2 out (fp32) for pool
__device__ float    g_as[NN];
__device__ float    g_ad[NN];
__device__ __align__(16) int g_cnt[2 * NN];
__device__ int      g_rowc[2 * NN + 1];       // concat exclusive scan
__device__ int      g_cur[2 * NN];
__device__ int      g_csrc[2 * EE];
__device__ unsigned g_w2b[64 * HID];          // W2 bf16x2 [k][n]
// lookback state (must be zero at kernel_launch entry; scatter re-zeroes)
__device__ int      g_ticket;
__device__ int      g_bflag[128];
__device__ int      g_bagg[128];
__device__ int      g_binc[128];

__device__ __forceinline__ uint2 pack4bf(float a, float b, float c, float d) {
    uint2 r;
    __nv_bfloat162 p0 = __float22bfloat162_rn(make_float2(a, b));
    __nv_bfloat162 p1 = __float22bfloat162_rn(make_float2(c, d));
    r.x = *(unsigned*)&p0;
    r.y = *(unsigned*)&p1;
    return r;
}

__device__ __forceinline__ float4 unpack4bf(uint2 v) {
    float2 f0 = __bfloat1622float2(*(__nv_bfloat162*)&v.x);
    float2 f1 = __bfloat1622float2(*(__nv_bfloat162*)&v.y);
    return make_float4(f0.x, f0.y, f1.x, f1.y);
}

// ---------------------------------------------------------------------------
// Fused: layer-1 transform (+ attention dots + W2 convert) || both histograms.
// Blocks [0, TB): transform. Blocks [TB, ...): histogram, 4 edges/thread.
__global__ void transform_hist_kernel(const float* __restrict__ x, const float* __restrict__ W,
                                      const float* __restrict__ atts, const float* __restrict__ attd,
                                      const int* __restrict__ dst_s, const int* __restrict__ dst_t,
                                      const float* __restrict__ W2, int N, int E, int TB) {
    if ((int)blockIdx.x < TB) {
        int gid = blockIdx.x * 256 + threadIdx.x;
        if (gid < 64 * HID) {   // W2 -> bf16 (8192 threads)
            float2 v = *(const float2*)(W2 + gid * 2);
            __nv_bfloat162 p = __float22bfloat162_rn(v);
            g_w2b[gid] = *(unsigned*)&p;
        }
        int node = gid >> 5;
        int lane = threadIdx.x & 31;
        if (node >= N) return;
        float xv = (lane < 9) ? x[(size_t)node * 9 + lane] : 0.f;
        float4 acc = make_float4(0.f, 0.f, 0.f, 0.f);
#pragma unroll
        for (int k = 0; k < 9; k++) {
            float xk = __shfl_sync(0xffffffffu, xv, k);
            float4 w = *(const float4*)(W + k * HID + lane * 4);
            acc.x = fmaf(xk, w.x, acc.x);
            acc.y = fmaf(xk, w.y, acc.y);
            acc.z = fmaf(xk, w.z, acc.z);
            acc.w = fmaf(xk, w.w, acc.w);
        }
        g_hb[(size_t)node * 32 + lane] = pack4bf(acc.x, acc.y, acc.z, acc.w);
        float4 s4 = *(const float4*)(atts + lane * 4);
        float4 d4 = *(const float4*)(attd + lane * 4);
        float ps = acc.x * s4.x + acc.y * s4.y + acc.z * s4.z + acc.w * s4.w;
        float pd = acc.x * d4.x + acc.y * d4.y + acc.z * d4.z + acc.w * d4.w;
#pragma unroll
        for (int off = 16; off >= 1; off >>= 1) {
            ps += __shfl_xor_sync(0xffffffffu, ps, off);
            pd += __shfl_xor_sync(0xffffffffu, pd, off);
        }
        if (lane == 0) { g_as[node] = ps; g_ad[node] = pd; }
    } else {
        int ES4 = (E + 3) >> 2;
        int idx = (blockIdx.x - TB) * 256 + threadIdx.x;
        const int* dsa;
        int base, off0;
        if (idx < ES4)            { dsa = dst_s; base = idx * 4;          off0 = 0; }
        else if (idx < 2 * ES4)   { dsa = dst_t; base = (idx - ES4) * 4;  off0 = NN; }
        else return;
        if (base + 3 < E) {
            int4 d = *(const int4*)(dsa + base);
            atomicAdd(&g_cnt[off0 + d.x], 1);
            atomicAdd(&g_cnt[off0 + d.y], 1);
            atomicAdd(&g_cnt[off0 + d.z], 1);
            atomicAdd(&g_cnt[off0 + d.w], 1);
        } else {
            for (int j = base; j < E; ++j) atomicAdd(&g_cnt[off0 + dsa[j]], 1);
        }
    }
}

// ---------------------------------------------------------------------------
// Single-pass decoupled-lookback exclusive scan over g_cnt[0..n2) -> g_rowc/g_cur.
// Requires g_ticket == 0 and g_bflag[] == 0 at entry. nb blocks, all co-resident.
__global__ __launch_bounds__(1024) void scan_kernel(int n2, int nb) {
    __shared__ int sbid_sh, s_total, s_prefix;
    __shared__ int ws[32];
    int t = threadIdx.x, lane = t & 31, w = t >> 5;
    if (t == 0) sbid_sh = atomicAdd(&g_ticket, 1);
    __syncthreads();
    int bid = sbid_sh;
    int base = bid * SCAN_ELEMS;
    int i0 = base + t * 2;
    int2 v = make_int2(0, 0);
    if (i0 + 1 < n2) v = *(const int2*)&g_cnt[i0];
    else if (i0 < n2) v.x = g_cnt[i0];
    int local = v.x + v.y;
    int xv = local;
#pragma unroll
    for (int off = 1; off < 32; off <<= 1) {
        int u = __shfl_up_sync(0xffffffffu, xv, off);
        if (lane >= off) xv += u;
    }
    if (lane == 31) ws[w] = xv;
    __syncthreads();
    if (w == 0) {
        int s = ws[lane];
        int y = s;
#pragma unroll
        for (int off = 1; off < 32; off <<= 1) {
            int u = __shfl_up_sync(0xffffffffu, y, off);
            if (lane >= off) y += u;
        }
        ws[lane] = y - s;
        if (lane == 31) s_total = y;
    }
    __syncthreads();
    int thr_incl = xv + ws[w];
    int btotal = s_total;

    if (t == 0) {
        if (bid == 0) {
            g_binc[0] = btotal;
            __threadfence();
            atomicExch(&g_bflag[0], 2);
        } else {
            g_bagg[bid] = btotal;
            __threadfence();
            atomicExch(&g_bflag[bid], 1);
        }
    }
    if (t < 32) {
        int pre = 0;
        if (bid > 0) {
            int jbase = bid - 1;
            while (true) {
                int j = jbase - lane;
                int f = 0;
                if (j >= 0) {
                    do { f = atomicAdd(&g_bflag[j], 0); } while (f == 0);
                }
                int val = 0;
                if (j >= 0)
                    val = (f == 2) ? atomicAdd(&g_binc[j], 0) : atomicAdd(&g_bagg[j], 0);
                unsigned pm = __ballot_sync(0xffffffffu, j >= 0 && f == 2);
                if (pm) {
                    int fp = __ffs(pm) - 1;
                    int contrib = (lane <= fp) ? val : 0;
#pragma unroll
                    for (int off = 16; off >= 1; off >>= 1)
                        contrib += __shfl_xor_sync(0xffffffffu, contrib, off);
                    pre += contrib;
                    break;
                } else {
                    int contrib = val;
#pragma unroll
                    for (int off = 16; off >= 1; off >>= 1)
                        contrib += __shfl_xor_sync(0xffffffffu, contrib, off);
                    pre += contrib;
                    jbase -= 32;
                }
            }
            if (lane == 0) {
                g_binc[bid] = pre + btotal;
                __threadfence();
                atomicExch(&g_bflag[bid], 2);
            }
        }
        if (lane == 0) s_prefix = pre;
    }
    __syncthreads();
    int pfx = s_prefix;
    int excl = pfx + thr_incl - local;
    if (i0 < n2) { g_rowc[i0] = excl; g_cur[i0] = excl; }
    if (i0 + 1 < n2) { g_rowc[i0 + 1] = excl + v.x; g_cur[i0 + 1] = excl + v.x; }
    if (bid == nb - 1 && t == 0) g_rowc[n2] = pfx + btotal;
}

// ---------------------------------------------------------------------------
// Both scatters in one launch + reset lookback/cnt state for the next call.
__global__ void scatter_kernel(const int* __restrict__ src_s, const int* __restrict__ dst_s,
                               const int* __restrict__ src_t, const int* __restrict__ dst_t,
                               int E, int n2) {
    int i = blockIdx.x * 256 + threadIdx.x;
    if (i < E) {
        int p = atomicAdd(&g_cur[dst_s[i]], 1);
        g_csrc[p] = src_s[i];
    } else if (i < 2 * E) {
        int k = i - E;
        int p = atomicAdd(&g_cur[NN + dst_t[k]], 1);
        g_csrc[p] = src_t[k];
    }
    // cleanup for next graph replay (scan outputs already consumed via g_cur)
    if (i < n2) g_cnt[i] = 0;
    if (i < 128) g_bflag[i] = 0;
    if (i == 0) g_ticket = 0;
}

// ---------------------------------------------------------------------------
// Two-phase aggregation. One warp per dst node.
template <int LAYER>
__global__ void aggregate_kernel(const float* __restrict__ bias, int n) {
    int node = (blockIdx.x * blockDim.x + threadIdx.x) >> 5;
    int lane = threadIdx.x & 31;
    if (node >= n) return;
    const int* rowb = g_rowc + LAYER * NN;
    int start = rowb[node], end = rowb[node + 1];
    float4 b = *(const float4*)(bias + lane * 4);

    if (start == end) {
        float4 o = b;
        if (LAYER == 0) {
            o.x = fmaxf(o.x, 0.f); o.y = fmaxf(o.y, 0.f);
            o.z = fmaxf(o.z, 0.f); o.w = fmaxf(o.w, 0.f);
            g_ab[(size_t)node * 32 + lane] = pack4bf(o.x, o.y, o.z, o.w);
        } else {
            *(float4*)(g_acc + (size_t)node * HID + lane * 4) = o;
        }
        return;
    }

    float ad = g_ad[node];
    float m = -INFINITY;
    for (int bi = start + lane; bi < end; bi += 32) {
        int s = g_csrc[bi];
        float a = g_as[s] + ad;
        a = (a >= 0.f) ? a : 0.2f * a;
        m = fmaxf(m, a);
    }
#pragma unroll
    for (int off = 16; off >= 1; off >>= 1)
        m = fmaxf(m, __shfl_xor_sync(0xffffffffu, m, off));

    float ssum = 0.f;
    float4 acc = make_float4(0.f, 0.f, 0.f, 0.f);
    for (int basei = start; basei < end; basei += 32) {
        int nloc = min(32, end - basei);
        int srcl = 0;
        float wv = 0.f;
        if (lane < nloc) {
            srcl = g_csrc[basei + lane];
            float a = g_as[srcl] + ad;
            a = (a >= 0.f) ? a : 0.2f * a;
            wv = __expf(a - m);
        }
        ssum += wv;
#pragma unroll 8
        for (int t = 0; t < nloc; ++t) {
            int sidx = __shfl_sync(0xffffffffu, srcl, t);
            float wt = __shfl_sync(0xffffffffu, wv, t);
            float4 hv = unpack4bf(g_hb[(size_t)sidx * 32 + lane]);
            acc.x = fmaf(wt, hv.x, acc.x);
            acc.y = fmaf(wt, hv.y, acc.y);
            acc.z = fmaf(wt, hv.z, acc.z);
            acc.w = fmaf(wt, hv.w, acc.w);
        }
    }
#pragma unroll
    for (int off = 16; off >= 1; off >>= 1)
        ssum += __shfl_xor_sync(0xffffffffu, ssum, off);

    float inv = 1.f / (ssum + 1e-16f);
    float4 o;
    o.x = fmaf(acc.x, inv, b.x);
    o.y = fmaf(acc.y, inv, b.y);
    o.z = fmaf(acc.z, inv, b.z);
    o.w = fmaf(acc.w, inv, b.w);
    if (LAYER == 0) {
        o.x = fmaxf(o.x, 0.f); o.y = fmaxf(o.y, 0.f);
        o.z = fmaxf(o.z, 0.f); o.w = fmaxf(o.w, 0.f);
        g_ab[(size_t)node * 32 + lane] = pack4bf(o.x, o.y, o.z, o.w);
    } else {
        *(float4*)(g_acc + (size_t)node * HID + lane * 4) = o;
    }
}

// ---------------------------------------------------------------------------
// Tensor-core GEMM: h2[M,128] = g_ab(bf16) @ g_w2b, fp32 accum.
// BM=128, 256 thr. Epilogue: bf16 store to g_hb + fused attention dots.
__global__ __launch_bounds__(256) void gemm_mma_kernel(const float* __restrict__ atts,
                                                       const float* __restrict__ attd, int M) {
    __shared__ __nv_bfloat16 As[128 * 72];
    __shared__ __nv_bfloat16 Bs[64 * 136];
    int tid = threadIdx.x;
    int lane = tid & 31, w = tid >> 5;
    int m0 = blockIdx.x * 128;
    float c[16][4];
#pragma unroll
    for (int i = 0; i < 16; i++)
#pragma unroll
        for (int j = 0; j < 4; j++) c[i][j] = 0.f;

    const char* abase = (const char*)g_ab;
    const char* bbase = (const char*)g_w2b;
    int grp = lane >> 3;
    int mw = w * 16;

    for (int ks = 0; ks < 2; ++ks) {
#pragma unroll
        for (int it = 0; it < 4; ++it) {
            int idx = tid + it * 256;
            int r = idx >> 3, c8 = idx & 7;
            uint4 v = make_uint4(0, 0, 0, 0);
            if (m0 + r < M)
                v = *(const uint4*)(abase + (size_t)(m0 + r) * 256 + ks * 128 + c8 * 16);
            *(uint4*)((char*)As + r * 144 + c8 * 16) = v;
        }
#pragma unroll
        for (int it = 0; it < 4; ++it) {
            int idx = tid + it * 256;
            int r = idx >> 4, c16 = idx & 15;
            uint4 v = *(const uint4*)(bbase + (size_t)(ks * 64 + r) * 256 + c16 * 16);
            *(uint4*)((char*)Bs + r * 272 + c16 * 16) = v;
        }
        __syncthreads();

#pragma unroll
        for (int kk = 0; kk < 64; kk += 16) {
            int arow = mw + (lane & 7) + (grp & 1) * 8;
            int acol = kk + (grp >> 1) * 8;
            uint32_t aaddr = (uint32_t)__cvta_generic_to_shared(As) + arow * 144 + acol * 2;
            uint32_t a0, a1, a2, a3;
            asm volatile("ldmatrix.sync.aligned.m8n8.x4.shared.b16 {%0,%1,%2,%3}, [%4];"
                         : "=r"(a0), "=r"(a1), "=r"(a2), "=r"(a3) : "r"(aaddr));
#pragma unroll
            for (int np = 0; np < 8; ++np) {
                int brow = kk + (lane & 7) + (grp & 1) * 8;
                int bcol = np * 16 + (grp >> 1) * 8;
                uint32_t baddr = (uint32_t)__cvta_generic_to_shared(Bs) + brow * 272 + bcol * 2;
                uint32_t b0, b1, b2, b3;
                asm volatile("ldmatrix.sync.aligned.m8n8.x4.trans.shared.b16 {%0,%1,%2,%3}, [%4];"
                             : "=r"(b0), "=r"(b1), "=r"(b2), "=r"(b3) : "r"(baddr));
                asm volatile("mma.sync.aligned.m16n8k16.row.col.f32.bf16.bf16.f32 "
                             "{%0,%1,%2,%3}, {%4,%5,%6,%7}, {%8,%9}, {%0,%1,%2,%3};"
                             : "+f"(c[2 * np][0]), "+f"(c[2 * np][1]),
                               "+f"(c[2 * np][2]), "+f"(c[2 * np][3])
                             : "r"(a0), "r"(a1), "r"(a2), "r"(a3), "r"(b0), "r"(b1));
                asm volatile("mma.sync.aligned.m16n8k16.row.col.f32.bf16.bf16.f32 "
                             "{%0,%1,%2,%3}, {%4,%5,%6,%7}, {%8,%9}, {%0,%1,%2,%3};"
                             : "+f"(c[2 * np + 1][0]), "+f"(c[2 * np + 1][1]),
                               "+f"(c[2 * np + 1][2]), "+f"(c[2 * np + 1][3])
                             : "r"(a0), "r"(a1), "r"(a2), "r"(a3), "r"(b2), "r"(b3));
            }
        }
        __syncthreads();
    }

    int r = lane >> 2, q = lane & 3;
    int row1 = m0 + mw + r, row2 = row1 + 8;
    unsigned* hb32 = (unsigned*)g_hb;
    float ps1 = 0.f, pd1 = 0.f, ps2 = 0.f, pd2 = 0.f;
#pragma unroll
    for (int nt = 0; nt < 16; ++nt) {
        int col = nt * 8 + q * 2;
        float2 sa = *(const float2*)(atts + col);
        float2 da = *(const float2*)(attd + col);
        ps1 += c[nt][0] * sa.x + c[nt][1] * sa.y;
        pd1 += c[nt][0] * da.x + c[nt][1] * da.y;
        ps2 += c[nt][2] * sa.x + c[nt][3] * sa.y;
        pd2 += c[nt][2] * da.x + c[nt][3] * da.y;
        if (row1 < M) {
            __nv_bfloat162 p = __float22bfloat162_rn(make_float2(c[nt][0], c[nt][1]));
            hb32[(size_t)row1 * 64 + nt * 4 + q] = *(unsigned*)&p;
        }
        if (row2 < M) {
            __nv_bfloat162 p = __float22bfloat162_rn(make_float2(c[nt][2], c[nt][3]));
            hb32[(size_t)row2 * 64 + nt * 4 + q] = *(unsigned*)&p;
        }
    }
#pragma unroll
    for (int off = 1; off <= 2; off <<= 1) {
        ps1 += __shfl_xor_sync(0xffffffffu, ps1, off);
        pd1 += __shfl_xor_sync(0xffffffffu, pd1, off);
        ps2 += __shfl_xor_sync(0xffffffffu, ps2, off);
        pd2 += __shfl_xor_sync(0xffffffffu, pd2, off);
    }
    if (q == 0) {
        if (row1 < M) { g_as[row1] = ps1; g_ad[row1] = pd1; }
        if (row2 < M) { g_as[row2] = ps2; g_ad[row2] = pd2; }
    }
}

// ---------------------------------------------------------------------------
__global__ __launch_bounds__(512) void pool_kernel(const int* __restrict__ batch,
                                                   const float* __restrict__ Wc,
                                                   const float* __restrict__ bc,
                                                   float* __restrict__ out, int N) {
    int g = blockIdx.x;
    int t = threadIdx.x;
    int c = t & 127;
    int part = t >> 7;
    int lo = 0, hi = N;
    while (lo < hi) { int mid = (lo + hi) >> 1; if (batch[mid] < g) lo = mid + 1; else hi = mid; }
    int start = lo;
    hi = N;
    while (lo < hi) { int mid = (lo + hi) >> 1; if (batch[mid] < g + 1) lo = mid + 1; else hi = mid; }
    int end = lo;

    float sum = 0.f;
    for (int nd = start + part; nd < end; nd += 4) sum += g_acc[(size_t)nd * HID + c];
    __shared__ float sh[512];
    sh[t] = sum;
    __syncthreads();
    if (t < 128) {
        float s = sh[t] + sh[t + 128] + sh[t + 256] + sh[t + 384];
        float cnt = (float)(end - start);
        if (cnt < 1.f) cnt = 1.f;
        float p = s / cnt;
        sh[t] = p * Wc[c * 2 + 0];
        sh[t + 128] = p * Wc[c * 2 + 1];
    }
    __syncthreads();
    for (int off = 64; off >= 1; off >>= 1) {
        if (t < off) { sh[t] += sh[t + off]; sh[128 + t] += sh[128 + t + off]; }
        __syncthreads();
    }
    if (t == 0) {
        float l0 = sh[0] + bc[0];
        float l1 = sh[128] + bc[1];
        float mx = fmaxf(l0, l1);
        float lse = mx + logf(expf(l0 - mx) + expf(l1 - mx));
        out[g * 2 + 0] = l0 - lse;
        out[g * 2 + 1] = l1 - lse;
    }
}

// ---------------------------------------------------------------------------
extern "C" void kernel_launch(void* const* d_in, const int* in_sizes, int n_in,
                              void* d_out, int out_size) {
    const float* x      = (const float*)d_in[0];
    const int*   ei_s   = (const int*)d_in[1];
    const int*   ei_t   = (const int*)d_in[3];
    const int*   batch  = (const int*)d_in[5];
    const float* W1     = (const float*)d_in[6];
    const float* atts1  = (const float*)d_in[7];
    const float* attd1  = (const float*)d_in[8];
    const float* b1     = (const float*)d_in[9];
    const float* W2     = (const float*)d_in[10];
    const float* atts2  = (const float*)d_in[11];
    const float* attd2  = (const float*)d_in[12];
    const float* b2     = (const float*)d_in[13];
    const float* Wc     = (const float*)d_in[14];
    const float* bc     = (const float*)d_in[15];
    float* out = (float*)d_out;

    const int N = in_sizes[0] / 9;
    const int E = in_sizes[1] / 2;
    const int G = out_size / 2;
    const int n2 = 2 * N;

    int warp_blocks = (N * 32 + 255) / 256;
    int TB = warp_blocks;
    int ES4 = (E + 3) / 4;
    int HB = (2 * ES4 + 255) / 256;
    int nb_scan = (n2 + SCAN_ELEMS - 1) / SCAN_ELEMS;

    // 1: transform1 || histograms || W2 convert
    transform_hist_kernel<<<TB + HB, 256>>>(x, W1, atts1, attd1,
                                            ei_s + E, ei_t + E, W2, N, E, TB);
    // 2: single-pass scan (decoupled lookback)
    scan_kernel<<<nb_scan, 1024>>>(n2, nb_scan);
    // 3: both scatters + state reset
    scatter_kernel<<<(2 * E + 255) / 256, 256>>>(ei_s, ei_s + E, ei_t, ei_t + E, E, n2);
    // 4: layer-1 aggregation
    aggregate_kernel<0><<<warp_blocks, 256>>>(b1, N);
    // 5: layer-2 transform (tensor cores) + fused attention dots
    gemm_mma_kernel<<<(N + 127) / 128, 256>>>(atts2, attd2, N);
    // 6: layer-2 aggregation
    aggregate_kernel<1><<<warp_blocks, 256>>>(b2, N);
    // 7: pool + classify + log_softmax
    pool_kernel<<<G, 512>>>(batch, Wc, bc, out, N);
}